// round 9
// baseline (speedup 1.0000x reference)
#include <cuda_runtime.h>
#include <math.h>

// Problem constants
#define BB 64
#define JJ 42
#define PP 16384
#define JG 3            // joint groups
#define JT 14           // joints per group (JG*JT == JJ)
#define PC 4            // P chunks
#define PPB (PP/PC)     // 4096 points per block
#define THREADS 256
#define NF4 (PPB*3/4)   // 3072 float4 per block tile
#define NWARP (THREADS/32)
#define GRID (BB*JG*PC)     // 768 blocks
#define NBJ (BB*JJ)         // 2688

// Scratch: per-(b,j) partial min-squared-distance, one slot per P-chunk.
__device__ float g_partial[NBJ * PC];
__device__ unsigned int g_count;   // zero at module load; last block resets to 0

__global__ __launch_bounds__(THREADS, 2) void sdl_fused_kernel(
    const float* __restrict__ pred,   // [B,J,3]
    const float* __restrict__ pts,    // [B,P,3]
    const float* __restrict__ gt,     // [B,J]
    float* __restrict__ out)
{
    // 48KB point tile; reduction scratch aliases it after the main loop.
    __shared__ float4 s_pts4[NF4];

    const int blk = blockIdx.x;
    const int pc = blk % PC;
    const int jg = (blk / PC) % JG;
    const int b  = blk / (PC * JG);
    const int t  = threadIdx.x;

    // ---- Stage points: perfectly coalesced LDG.128 (lane-consecutive float4) ----
    const float4* src = (const float4*)(pts + ((size_t)b * PP + (size_t)pc * PPB) * 3);
#pragma unroll
    for (int k = 0; k < NF4 / THREADS; k++)
        s_pts4[k * THREADS + t] = src[k * THREADS + t];

    // Joint constants in registers (a2 recomputed in epilogue).
    float mx[JT], my[JT], mz[JT], acc[JT];
    const float* jp = pred + (size_t)(b * JJ + jg * JT) * 3;
#pragma unroll
    for (int j = 0; j < JT; j++) {
        mx[j] = -2.0f * jp[j * 3 + 0];
        my[j] = -2.0f * jp[j * 3 + 1];
        mz[j] = -2.0f * jp[j * 3 + 2];
        acc[j] = 3.0e38f;
    }
    __syncthreads();

    // ---- Main loop: points from SMEM (conflict-free LDS.128, 48B lane stride) ----
#pragma unroll 1
    for (int it = 0; it < PPB / (4 * THREADS); it++) {
        const int g3 = (it * THREADS + t) * 3;
        float4 A  = s_pts4[g3 + 0];
        float4 Bv = s_pts4[g3 + 1];
        float4 C  = s_pts4[g3 + 2];

        float px[4], py[4], pz[4], b2[4];
        px[0] = A.x;  py[0] = A.y;  pz[0] = A.z;
        px[1] = A.w;  py[1] = Bv.x; pz[1] = Bv.y;
        px[2] = Bv.z; py[2] = Bv.w; pz[2] = C.x;
        px[3] = C.y;  py[3] = C.z;  pz[3] = C.w;
#pragma unroll
        for (int q = 0; q < 4; q++)
            b2[q] = fmaf(pz[q], pz[q], fmaf(py[q], py[q], px[q] * px[q]));

#pragma unroll
        for (int q = 0; q < 4; q++) {
#pragma unroll
            for (int j = 0; j < JT; j++) {
                float tq = fmaf(mx[j], px[q],
                            fmaf(my[j], py[q],
                             fmaf(mz[j], pz[q], b2[q])));
                acc[j] = fminf(acc[j], tq);
            }
        }
    }

    // Epilogue: fold |a|^2 (recompute from pred; constant shift commutes with min).
#pragma unroll
    for (int j = 0; j < JT; j++) {
        float ax = jp[j * 3 + 0];
        float ay = jp[j * 3 + 1];
        float az = jp[j * 3 + 2];
        acc[j] += fmaf(az, az, fmaf(ay, ay, ax * ax));
    }

    // Warp min-reduce.
#pragma unroll
    for (int j = 0; j < JT; j++) {
        float v = acc[j];
        v = fminf(v, __shfl_xor_sync(0xFFFFFFFFu, v, 16));
        v = fminf(v, __shfl_xor_sync(0xFFFFFFFFu, v, 8));
        v = fminf(v, __shfl_xor_sync(0xFFFFFFFFu, v, 4));
        v = fminf(v, __shfl_xor_sync(0xFFFFFFFFu, v, 2));
        v = fminf(v, __shfl_xor_sync(0xFFFFFFFFu, v, 1));
        acc[j] = v;
    }

    // Reuse the smem tile as reduction scratch (all LDS reads are done after this sync).
    __syncthreads();
    float* sred = (float*)s_pts4;           // [0..111]: smin[8][14]
    unsigned* sflag = ((unsigned*)s_pts4) + 120;  // flag slot
    float* ssum = ((float*)s_pts4) + 128;   // [128..135]: per-warp sums

    const int w = t >> 5, l = t & 31;
    if (l == 0) {
#pragma unroll
        for (int j = 0; j < JT; j++) sred[w * JT + j] = acc[j];
    }
    __syncthreads();

    if (t < JT) {
        float v = sred[t];
#pragma unroll
        for (int wi = 1; wi < NWARP; wi++) v = fminf(v, sred[wi * JT + t]);
        g_partial[(size_t)(b * JJ + jg * JT + t) * PC + pc] = v;
    }

    // ---- last-block finalize (fused MSE) ----
    __threadfence();
    __syncthreads();
    if (t == 0) {
        unsigned c = atomicAdd(&g_count, 1u);
        *sflag = (c == (unsigned)(GRID - 1)) ? 1u : 0u;
    }
    __syncthreads();
    if (*sflag == 0u) return;

    // Last block: all partials globally visible (L2-hot).
    float s = 0.0f;
    const float4* gp = (const float4*)g_partial;
#pragma unroll 1
    for (int i = t; i < NBJ; i += THREADS) {
        float4 v = __ldcg(gp + i);
        float m = fminf(fminf(v.x, v.y), fminf(v.z, v.w));
        m = fmaxf(m, 0.0f);
        float d = sqrtf(m) - gt[i];
        s = fmaf(d, d, s);
    }
    // Deterministic fixed-order reduction.
    s += __shfl_xor_sync(0xFFFFFFFFu, s, 16);
    s += __shfl_xor_sync(0xFFFFFFFFu, s, 8);
    s += __shfl_xor_sync(0xFFFFFFFFu, s, 4);
    s += __shfl_xor_sync(0xFFFFFFFFu, s, 2);
    s += __shfl_xor_sync(0xFFFFFFFFu, s, 1);
    __syncthreads();
    if (l == 0) ssum[w] = s;
    __syncthreads();
    if (t == 0) {
        float tot = ssum[0];
#pragma unroll
        for (int wi = 1; wi < NWARP; wi++) tot += ssum[wi];
        out[0] = tot / (float)NBJ;
        g_count = 0;   // reset for next graph replay
    }
}

extern "C" void kernel_launch(void* const* d_in, const int* in_sizes, int n_in,
                              void* d_out, int out_size) {
    (void)in_sizes; (void)n_in; (void)out_size;
    const float* pred = (const float*)d_in[0];   // [64,42,3]
    const float* pts  = (const float*)d_in[1];   // [64,16384,3]
    const float* gt   = (const float*)d_in[2];   // [64,42]
    float* out = (float*)d_out;

    sdl_fused_kernel<<<GRID, THREADS>>>(pred, pts, gt, out);
}